// round 1
// baseline (speedup 1.0000x reference)
#include <cuda_runtime.h>
#include <cstdint>

// ---------------- problem constants (match reference exactly) ----------------
#define BB   4
#define NPTS 300000
#define NC   5
#define GXX  432
#define GYY  496
#define GZZ  1
#define NVOX (GXX * GYY * GZZ)          // 214272
#define MAXV 40000
#define MAXP 30
#define CAP  48                          // per-voxel index bucket capacity
#define CHUNK 1024
#define NB   ((NVOX + CHUNK - 1) / CHUNK)   // 210

#define FEATS_ELEMS ((size_t)BB * MAXV * MAXP * NC)   // 24,000,000
#define COORD_ELEMS ((size_t)BB * MAXV * 4)           // 640,000

// ---------------- static device scratch (no allocations allowed) -------------
__device__ int g_count [BB * NVOX];            // points per (b, voxel)
__device__ int g_bucket[(size_t)BB * NVOX * CAP];  // point indices (atomic order)
__device__ int g_rank  [BB * NVOX];            // within-chunk exclusive occupancy prefix
__device__ int g_bsum  [BB * NB];              // per-chunk occupancy totals
__device__ int g_boff  [BB * NB];              // exclusive prefix of chunk totals

// ---------------- pass 1: voxelize + bucket append ---------------------------
__global__ void k_points(const float* __restrict__ pts) {
    int tid = blockIdx.x * blockDim.x + threadIdx.x;
    if (tid >= BB * NPTS) return;
    int b = tid / NPTS;
    int n = tid - b * NPTS;
    const float* p = pts + (size_t)(b * NPTS + n) * NC;
    float x = p[0], y = p[1], z = p[2];
    // identical float32 ops as reference: floor((p - lo) / vs)
    int ix = (int)floorf((x - 0.0f)   / 0.16f);
    int iy = (int)floorf((y + 39.68f) / 0.16f);
    int iz = (int)floorf((z + 3.0f)   / 4.0f);
    if (ix < 0 || ix >= GXX || iy < 0 || iy >= GYY || iz < 0 || iz >= GZZ) return;
    int vid = (iz * GYY + iy) * GXX + ix;
    int cell = b * NVOX + vid;
    int pos = atomicAdd(&g_count[cell], 1);
    if (pos < CAP) g_bucket[(size_t)cell * CAP + pos] = n;
}

// ---------------- scan step 1: per-1024-chunk exclusive prefix ----------------
__global__ void k_scan1() {
    int blk = blockIdx.x;
    int b  = blk / NB;
    int cb = blk - b * NB;
    int t  = threadIdx.x;              // 256 threads, 4 flags each
    __shared__ int sh[256];
    const int* cnt = g_count + b * NVOX;
    int base = cb * CHUNK + t * 4;
    int f0 = 0, f1 = 0, f2 = 0, f3 = 0;
    if (base + 0 < NVOX) f0 = (cnt[base + 0] > 0);
    if (base + 1 < NVOX) f1 = (cnt[base + 1] > 0);
    if (base + 2 < NVOX) f2 = (cnt[base + 2] > 0);
    if (base + 3 < NVOX) f3 = (cnt[base + 3] > 0);
    int s = f0 + f1 + f2 + f3;
    sh[t] = s;
    __syncthreads();
    for (int off = 1; off < 256; off <<= 1) {   // Hillis–Steele inclusive
        int v = (t >= off) ? sh[t - off] : 0;
        __syncthreads();
        sh[t] += v;
        __syncthreads();
    }
    int excl = sh[t] - s;
    int* rk = g_rank + b * NVOX;
    int r = excl;
    if (base + 0 < NVOX) { rk[base + 0] = r; r += f0; }
    if (base + 1 < NVOX) { rk[base + 1] = r; r += f1; }
    if (base + 2 < NVOX) { rk[base + 2] = r; r += f2; }
    if (base + 3 < NVOX) { rk[base + 3] = r; r += f3; }
    if (t == 255) g_bsum[b * NB + cb] = sh[255];
}

// ---------------- scan step 2: exclusive prefix over chunk totals -------------
__global__ void k_scan2() {
    int b = blockIdx.x;
    int t = threadIdx.x;               // 256 >= NB
    __shared__ int sh[256];
    int v = (t < NB) ? g_bsum[b * NB + t] : 0;
    sh[t] = v;
    __syncthreads();
    for (int off = 1; off < 256; off <<= 1) {
        int u = (t >= off) ? sh[t - off] : 0;
        __syncthreads();
        sh[t] += u;
        __syncthreads();
    }
    if (t < NB) g_boff[b * NB + t] = sh[t] - v;
}

// ---------------- coords init: fill with -1.0 ---------------------------------
__global__ void k_coords_init(float* __restrict__ out) {
    int tid = blockIdx.x * blockDim.x + threadIdx.x;
    if (tid < (int)COORD_ELEMS) out[FEATS_ELEMS + tid] = -1.0f;
}

// ---------------- emit: sort bucket, write feats + coords ---------------------
__global__ void k_emit(const float* __restrict__ pts, float* __restrict__ out,
                       int write_coords) {
    int tid = blockIdx.x * blockDim.x + threadIdx.x;
    if (tid >= BB * NVOX) return;
    int b = tid / NVOX;
    int v = tid - b * NVOX;
    int cnt = g_count[tid];
    if (cnt == 0) return;
    int rank = g_rank[tid] + g_boff[b * NB + (v >> 10)];
    if (rank >= MAXV) return;                     // unique-voxel cap (reference drop)
    int row = b * MAXV + rank;

    if (write_coords) {
        float* co = out + FEATS_ELEMS + (size_t)row * 4;
        int iz  = v / (GXX * GYY);
        int rem = v - iz * (GXX * GYY);
        co[0] = (float)b;
        co[1] = (float)iz;
        co[2] = (float)(rem / GXX);
        co[3] = (float)(rem % GXX);
    }

    int m = cnt < CAP ? cnt : CAP;
    int a[CAP];
    const int* bk = g_bucket + (size_t)tid * CAP;
    for (int i = 0; i < m; i++) a[i] = bk[i];
    // insertion sort ascending -> original point order (deterministic ranks)
    for (int i = 1; i < m; i++) {
        int key = a[i];
        int j = i - 1;
        while (j >= 0 && a[j] > key) { a[j + 1] = a[j]; j--; }
        a[j + 1] = key;
    }
    int mm = m < MAXP ? m : MAXP;
    float* fo = out + (size_t)row * MAXP * NC;
    const float* pb = pts + (size_t)b * NPTS * NC;
    for (int r = 0; r < mm; r++) {
        const float* p = pb + (size_t)a[r] * NC;
        fo[r * NC + 0] = (p[0] - 0.0f)   / 69.12f;
        fo[r * NC + 1] = (p[1] + 39.68f) / 79.36f;
        fo[r * NC + 2] = (p[2] + 3.0f)   / 4.0f;
        fo[r * NC + 3] = p[3];
        fo[r * NC + 4] = p[4];
    }
}

// ---------------- launch ------------------------------------------------------
extern "C" void kernel_launch(void* const* d_in, const int* in_sizes, int n_in,
                              void* d_out, int out_size) {
    const float* pts = (const float*)d_in[0];
    float* out = (float*)d_out;

    void* pcount = nullptr;
    cudaGetSymbolAddress(&pcount, g_count);
    cudaMemsetAsync(pcount, 0, sizeof(int) * BB * NVOX);

    // feats region -> 0
    cudaMemsetAsync(out, 0, FEATS_ELEMS * sizeof(float));

    int write_coords = ((size_t)out_size >= FEATS_ELEMS + COORD_ELEMS);
    if (write_coords) {
        k_coords_init<<<((int)COORD_ELEMS + 255) / 256, 256>>>(out);
    }

    k_points<<<(BB * NPTS + 255) / 256, 256>>>(pts);
    k_scan1 <<<BB * NB, 256>>>();
    k_scan2 <<<BB, 256>>>();
    k_emit  <<<(BB * NVOX + 255) / 256, 256>>>(pts, out, write_coords);
}

// round 2
// speedup vs baseline: 1.0823x; 1.0823x over previous
#include <cuda_runtime.h>
#include <cstdint>

// ---------------- problem constants (match reference exactly) ----------------
#define BB   4
#define NPTS 300000
#define NC   5
#define GXX  432
#define GYY  496
#define GZZ  1
#define NVOX (GXX * GYY * GZZ)          // 214272
#define MAXV 40000
#define MAXP 30
#define CAP  48                          // per-voxel index bucket capacity
#define CHUNK 1024
#define NB   ((NVOX + CHUNK - 1) / CHUNK)   // 210

#define FEATS_ELEMS ((size_t)BB * MAXV * MAXP * NC)   // 24,000,000 floats
#define COORD_ELEMS ((size_t)BB * MAXV * 4)           // 640,000 floats

#define F4_FEATS (24000000 / 4)          // 6,000,000 float4
#define F4_COORD (640000 / 4)            // 160,000 float4
#define I4_CNT   ((BB * NVOX) / 4)       // 214,272 int4
#define I4_AGG   ((BB * NB + 3) / 4)     // 210 int4
#define FILL_TOTAL (F4_FEATS + F4_COORD + I4_CNT + I4_AGG)

#define VALIDF (1 << 30)

// ---------------- static device scratch (16B-aligned for vector ops) ----------
__device__ int4 g_count4[(BB * NVOX) / 4];
__device__ int4 g_agg4  [I4_AGG];
__device__ int  g_bucket[(size_t)BB * NVOX * CAP];
__device__ int  g_rank  [BB * NVOX];     // absolute rank after single-pass scan

#define G_COUNT ((int*)g_count4)
#define G_AGG   ((int*)g_agg4)

// ---------------- fused init: feats=0, coords=-1, counts=0, agg=0 -------------
__global__ void k_fill(float4* __restrict__ out4) {
    int i = blockIdx.x * blockDim.x + threadIdx.x;
    if (i < F4_FEATS) {
        out4[i] = make_float4(0.f, 0.f, 0.f, 0.f);
        return;
    }
    i -= F4_FEATS;
    if (i < F4_COORD) {
        out4[F4_FEATS + i] = make_float4(-1.f, -1.f, -1.f, -1.f);
        return;
    }
    i -= F4_COORD;
    if (i < I4_CNT) {
        g_count4[i] = make_int4(0, 0, 0, 0);
        return;
    }
    i -= I4_CNT;
    if (i < I4_AGG) {
        g_agg4[i] = make_int4(0, 0, 0, 0);
    }
}

// ---------------- pass 1: voxelize + bucket append ---------------------------
__global__ void k_points(const float* __restrict__ pts) {
    int tid = blockIdx.x * blockDim.x + threadIdx.x;
    if (tid >= BB * NPTS) return;
    int b = tid / NPTS;
    int n = tid - b * NPTS;
    const float* p = pts + (size_t)tid * NC;
    float x = __ldg(p + 0), y = __ldg(p + 1), z = __ldg(p + 2);
    // identical float32 ops as reference: floor((p - lo) / vs)
    int ix = (int)floorf((x - 0.0f)   / 0.16f);
    int iy = (int)floorf((y + 39.68f) / 0.16f);
    int iz = (int)floorf((z + 3.0f)   / 4.0f);
    if (ix < 0 || ix >= GXX || iy < 0 || iy >= GYY || iz < 0 || iz >= GZZ) return;
    int vid = (iz * GYY + iy) * GXX + ix;
    int cell = b * NVOX + vid;
    int pos = atomicAdd(&G_COUNT[cell], 1);
    if (pos < CAP) g_bucket[(size_t)cell * CAP + pos] = n;
}

// ---------------- single-pass scan with decoupled lookback --------------------
// 840 blocks (256 thr) all fit in one wave on 148 SMs -> spin-wait is safe.
__global__ void k_scan() {
    int blk = blockIdx.x;
    int b  = blk / NB;
    int cb = blk - b * NB;
    int t  = threadIdx.x;
    __shared__ int sh[256];

    const int* cnt = G_COUNT + b * NVOX;
    int base = cb * CHUNK + t * 4;
    int f0 = 0, f1 = 0, f2 = 0, f3 = 0;
    if (base + 0 < NVOX) f0 = (cnt[base + 0] > 0);
    if (base + 1 < NVOX) f1 = (cnt[base + 1] > 0);
    if (base + 2 < NVOX) f2 = (cnt[base + 2] > 0);
    if (base + 3 < NVOX) f3 = (cnt[base + 3] > 0);
    int s = f0 + f1 + f2 + f3;
    sh[t] = s;
    __syncthreads();
    #pragma unroll
    for (int off = 1; off < 256; off <<= 1) {   // Hillis–Steele inclusive
        int v = (t >= off) ? sh[t - off] : 0;
        __syncthreads();
        sh[t] += v;
        __syncthreads();
    }
    int incl  = sh[t];
    int excl  = incl - s;
    int total = sh[255];

    // publish this chunk's aggregate ASAP
    if (t == 0) atomicExch(&G_AGG[blk], total | VALIDF);

    // lookback: sum all predecessor aggregates (within this batch)
    int partial = 0;
    for (int j = t; j < cb; j += 256) {
        int v;
        do { v = atomicAdd(&G_AGG[b * NB + j], 0); } while (!(v & VALIDF));
        partial += (v & (VALIDF - 1));
    }
    __syncthreads();
    sh[t] = partial;
    __syncthreads();
    #pragma unroll
    for (int off = 128; off > 0; off >>= 1) {
        if (t < off) sh[t] += sh[t + off];
        __syncthreads();
    }
    int chunk_off = sh[0];

    int* rk = g_rank + b * NVOX;
    int r = chunk_off + excl;
    if (base + 0 < NVOX) { rk[base + 0] = r; r += f0; }
    if (base + 1 < NVOX) { rk[base + 1] = r; r += f1; }
    if (base + 2 < NVOX) { rk[base + 2] = r; r += f2; }
    if (base + 3 < NVOX) { rk[base + 3] = r; r += f3; }
}

// ---------------- emit: sort bucket, write feats + coords ---------------------
__global__ void k_emit(const float* __restrict__ pts, float* __restrict__ out) {
    int tid = blockIdx.x * blockDim.x + threadIdx.x;
    if (tid >= BB * NVOX) return;
    int b = tid / NVOX;
    int v = tid - b * NVOX;
    int cnt = __ldg(&G_COUNT[tid]);
    if (cnt == 0) return;
    int rank = g_rank[tid];
    if (rank >= MAXV) return;                     // unique-voxel cap (reference drop)
    int row = b * MAXV + rank;

    // coords (b, z, y, x) as one 16B store
    {
        int iz  = v / (GXX * GYY);
        int rem = v - iz * (GXX * GYY);
        float4* co = (float4*)(out + FEATS_ELEMS) + row;
        *co = make_float4((float)b, (float)iz, (float)(rem / GXX), (float)(rem % GXX));
    }

    int m = cnt < CAP ? cnt : CAP;
    int a[CAP];
    const int* bk = g_bucket + (size_t)tid * CAP;
    for (int i = 0; i < m; i++) a[i] = bk[i];
    // insertion sort ascending -> original point order (deterministic ranks)
    for (int i = 1; i < m; i++) {
        int key = a[i];
        int j = i - 1;
        while (j >= 0 && a[j] > key) { a[j + 1] = a[j]; j--; }
        a[j + 1] = key;
    }
    int mm = m < MAXP ? m : MAXP;
    float* fo = out + (size_t)row * MAXP * NC;
    const float* pb = pts + (size_t)b * NPTS * NC;
    for (int r = 0; r < mm; r++) {
        const float* p = pb + (size_t)a[r] * NC;
        fo[r * NC + 0] = (p[0] - 0.0f)   / 69.12f;
        fo[r * NC + 1] = (p[1] + 39.68f) / 79.36f;
        fo[r * NC + 2] = (p[2] + 3.0f)   / 4.0f;
        fo[r * NC + 3] = p[3];
        fo[r * NC + 4] = p[4];
    }
}

// ---------------- launch ------------------------------------------------------
extern "C" void kernel_launch(void* const* d_in, const int* in_sizes, int n_in,
                              void* d_out, int out_size) {
    const float* pts = (const float*)d_in[0];
    float* out = (float*)d_out;

    k_fill  <<<(FILL_TOTAL + 255) / 256, 256>>>((float4*)out);
    k_points<<<(BB * NPTS + 255) / 256, 256>>>(pts);
    k_scan  <<<BB * NB, 256>>>();
    k_emit  <<<(BB * NVOX + 255) / 256, 256>>>(pts, out);
}

// round 4
// speedup vs baseline: 1.0830x; 1.0007x over previous
#include <cuda_runtime.h>
#include <cstdint>
#include <climits>

// ---------------- problem constants (match reference exactly) ----------------
#define BB   4
#define NPTS 300000
#define NC   5
#define GXX  432
#define GYY  496
#define GZZ  1
#define NVOX (GXX * GYY * GZZ)          // 214272
#define MAXV 40000
#define MAXP 30
#define CAP  48                          // per-voxel index bucket capacity
#define CHUNK 1024
#define NB   ((NVOX + CHUNK - 1) / CHUNK)   // 210

#define FEATS_ELEMS ((size_t)BB * MAXV * MAXP * NC)   // 24,000,000 floats
#define COORD_ELEMS ((size_t)BB * MAXV * 4)           // 640,000 floats

#define I4_CNT   ((BB * NVOX) / 4)       // 214,272 int4
#define I4_AGG   ((BB * NB + 3) / 4)
#define I4_VL    ((BB * MAXV) / 4)       // 40,000 int4
#define FILL_TOTAL (I4_CNT + I4_AGG + I4_VL)

#define VALIDF (1 << 30)
#define ROWF   (MAXP * NC)               // 150 floats per feats row

// ---------------- static device scratch (16B-aligned for vector ops) ----------
__device__ int4 g_count4[(BB * NVOX) / 4];
__device__ int4 g_agg4  [I4_AGG];
__device__ int4 g_vlist4[I4_VL];         // row -> vid (or -1)
__device__ int  g_bucket[(size_t)BB * NVOX * CAP];

#define G_COUNT ((int*)g_count4)
#define G_AGG   ((int*)g_agg4)
#define G_VLIST ((int*)g_vlist4)

// ---------------- tiny init: counts=0, agg=0, vlist=-1 ------------------------
__global__ void k_fill() {
    int i = blockIdx.x * blockDim.x + threadIdx.x;
    if (i < I4_CNT) { g_count4[i] = make_int4(0, 0, 0, 0); return; }
    i -= I4_CNT;
    if (i < I4_AGG) { g_agg4[i] = make_int4(0, 0, 0, 0); return; }
    i -= I4_AGG;
    if (i < I4_VL)  { g_vlist4[i] = make_int4(-1, -1, -1, -1); }
}

// ---------------- pass 1: voxelize + bucket append ---------------------------
__global__ void k_points(const float* __restrict__ pts) {
    int tid = blockIdx.x * blockDim.x + threadIdx.x;
    if (tid >= BB * NPTS) return;
    int b = tid / NPTS;
    int n = tid - b * NPTS;
    const float* p = pts + (size_t)tid * NC;
    float x = __ldg(p + 0), y = __ldg(p + 1), z = __ldg(p + 2);
    // identical float32 ops as reference: floor((p - lo) / vs)
    int ix = (int)floorf((x - 0.0f)   / 0.16f);
    int iy = (int)floorf((y + 39.68f) / 0.16f);
    int iz = (int)floorf((z + 3.0f)   / 4.0f);
    if (ix < 0 || ix >= GXX || iy < 0 || iy >= GYY || iz < 0 || iz >= GZZ) return;
    int vid = (iz * GYY + iy) * GXX + ix;
    int cell = b * NVOX + vid;
    int pos = atomicAdd(&G_COUNT[cell], 1);
    if (pos < CAP) g_bucket[(size_t)cell * CAP + pos] = n;
}

// ---------------- single-pass scan with decoupled lookback --------------------
// 840 blocks (256 thr) all fit in one wave on 148 SMs -> spin-wait is safe.
// Produces the compact row -> vid list directly.
__global__ void k_scan() {
    int blk = blockIdx.x;
    int b  = blk / NB;
    int cb = blk - b * NB;
    int t  = threadIdx.x;
    __shared__ int sh[256];

    const int* cnt = G_COUNT + b * NVOX;
    int base = cb * CHUNK + t * 4;
    int f0 = 0, f1 = 0, f2 = 0, f3 = 0;
    if (base + 0 < NVOX) f0 = (cnt[base + 0] > 0);
    if (base + 1 < NVOX) f1 = (cnt[base + 1] > 0);
    if (base + 2 < NVOX) f2 = (cnt[base + 2] > 0);
    if (base + 3 < NVOX) f3 = (cnt[base + 3] > 0);
    int s = f0 + f1 + f2 + f3;
    sh[t] = s;
    __syncthreads();
    #pragma unroll
    for (int off = 1; off < 256; off <<= 1) {   // Hillis–Steele inclusive
        int v = (t >= off) ? sh[t - off] : 0;
        __syncthreads();
        sh[t] += v;
        __syncthreads();
    }
    int excl  = sh[t] - s;
    int total = sh[255];

    // publish this chunk's aggregate ASAP
    if (t == 0) atomicExch(&G_AGG[blk], total | VALIDF);

    // lookback: sum all predecessor aggregates (within this batch)
    int partial = 0;
    for (int j = t; j < cb; j += 256) {
        int v;
        do { v = atomicAdd(&G_AGG[b * NB + j], 0); } while (!(v & VALIDF));
        partial += (v & (VALIDF - 1));
    }
    __syncthreads();
    sh[t] = partial;
    __syncthreads();
    #pragma unroll
    for (int off = 128; off > 0; off >>= 1) {
        if (t < off) sh[t] += sh[t + off];
        __syncthreads();
    }
    int r = sh[0] + excl;

    int* vl = G_VLIST + b * MAXV;
    if (f0) { if (r < MAXV) vl[r] = base + 0; r++; }
    if (f1) { if (r < MAXV) vl[r] = base + 1; r++; }
    if (f2) { if (r < MAXV) vl[r] = base + 2; r++; }
    if (f3) { if (r < MAXV) vl[r] = base + 3; r++; }
}

// ---------------- emit: warp per output row -----------------------------------
// Row staged in shared memory, then flushed with 5 coalesced 128B STG rounds.
// Lane 31 writes the coords float4. Rows with no voxel get zeros / -1.
__global__ void k_emit(const float* __restrict__ pts, float* __restrict__ out) {
    int gw = (blockIdx.x * blockDim.x + threadIdx.x) >> 5;
    if (gw >= BB * MAXV) return;
    int lane = threadIdx.x & 31;
    int wloc = threadIdx.x >> 5;
    __shared__ int   s_idx[8][32];
    __shared__ float s_row[8][ROWF + 2];

    int row = gw;
    int b = row / MAXV;
    int vid = __ldg(&G_VLIST[row]);

    float* fo = out + (size_t)row * ROWF;
    float4* co = (float4*)(out + FEATS_ELEMS) + row;

    if (vid < 0) {
        #pragma unroll
        for (int i = lane; i < ROWF; i += 32) fo[i] = 0.0f;
        if (lane == 31) *co = make_float4(-1.f, -1.f, -1.f, -1.f);
        return;
    }

    int cell = b * NVOX + vid;
    int cnt = __ldg(&G_COUNT[cell]);
    int m = cnt < CAP ? cnt : CAP;
    const int* bk = g_bucket + (size_t)cell * CAP;

    int v0 = (lane < m)      ? __ldg(bk + lane)      : INT_MAX;
    int v1 = (lane + 32 < m) ? __ldg(bk + lane + 32) : INT_MAX;

    // rank = #smaller indices (indices distinct -> permutation of 0..m-1)
    int r0 = 0, r1 = 0;
    for (int j = 0; j < m; j++) {
        int vj = (j < 32) ? __shfl_sync(0xffffffffu, v0, j)
                          : __shfl_sync(0xffffffffu, v1, j - 32);
        r0 += (vj < v0);
        r1 += (vj < v1);
    }
    if (lane < m      && r0 < MAXP) s_idx[wloc][r0] = v0;
    if (lane + 32 < m && r1 < MAXP) s_idx[wloc][r1] = v1;
    __syncwarp();

    int mm = m < MAXP ? m : MAXP;
    // stage the row: lane l computes point l's 5 features (stride-5 smem, 5 odd
    // -> conflict-free), zero-pad the rest
    if (lane < MAXP) {
        float* sr = &s_row[wloc][lane * NC];
        if (lane < mm) {
            int idx = s_idx[wloc][lane];
            const float* p = pts + ((size_t)b * NPTS + idx) * NC;
            float x = __ldg(p + 0), y = __ldg(p + 1), z = __ldg(p + 2);
            float f3 = __ldg(p + 3), f4 = __ldg(p + 4);
            sr[0] = (x - 0.0f)   / 69.12f;
            sr[1] = (y + 39.68f) / 79.36f;
            sr[2] = (z + 3.0f)   / 4.0f;
            sr[3] = f3;
            sr[4] = f4;
        } else {
            #pragma unroll
            for (int c = 0; c < NC; c++) sr[c] = 0.0f;
        }
    }
    __syncwarp();
    // coalesced flush: 5 rounds of consecutive 128B stores
    #pragma unroll
    for (int i = lane; i < ROWF; i += 32) fo[i] = s_row[wloc][i];

    if (lane == 31) {
        int iz  = vid / (GXX * GYY);
        int rem = vid - iz * (GXX * GYY);
        *co = make_float4((float)b, (float)iz, (float)(rem / GXX), (float)(rem % GXX));
    }
}

// ---------------- launch ------------------------------------------------------
extern "C" void kernel_launch(void* const* d_in, const int* in_sizes, int n_in,
                              void* d_out, int out_size) {
    const float* pts = (const float*)d_in[0];
    float* out = (float*)d_out;

    k_fill  <<<(FILL_TOTAL + 255) / 256, 256>>>();
    k_points<<<(BB * NPTS + 255) / 256, 256>>>(pts);
    k_scan  <<<BB * NB, 256>>>();
    k_emit  <<<(BB * MAXV * 32 + 255) / 256, 256>>>(pts, out);
}